// round 6
// baseline (speedup 1.0000x reference)
#include <cuda_runtime.h>
#include <cuda_bf16.h>
#include <cstdint>
#include <cstddef>

#define B_ 32
#define T_ 64
#define S_ 64
#define H_ 256
#define V_ 32000

// ---------------- device scratch (no runtime allocations allowed) ----------------
__device__ __align__(16) float g_annproj[B_ * S_ * H_];      // ann @ W1[H:] + b1
__device__ __align__(16) float g_xWi[B_ * T_ * 3 * H_];      // emb[tok] @ Wi*[H:] + bi*
__device__ __align__(16) float g_hidden[B_ * T_ * H_];       // scan outputs (GEMM A)

// =========================================================================
// Kernel 1: precompute annproj and xWi.  8 output rows per block,
// A rows staged in SMEM (broadcast reads), weights streamed coalesced.
// grid.x = 1024: kind = bid>>8 (0=ann,1=z,2=r,3=h), tile = bid&255.
// =========================================================================
__global__ __launch_bounds__(256) void prep_kernel(
    const int* __restrict__ inputs, const float* __restrict__ ann,
    const float* __restrict__ emb,
    const float* __restrict__ W1,  const float* __restrict__ b1,
    const float* __restrict__ Wiz, const float* __restrict__ biz,
    const float* __restrict__ Wir, const float* __restrict__ bir,
    const float* __restrict__ Wih, const float* __restrict__ bih)
{
    __shared__ float a_s[8][H_];
    __shared__ int s_tok[8];
    const int tid  = threadIdx.x;
    const int kind = blockIdx.x >> 8;
    const int r0   = (blockIdx.x & 255) * 8;

    if (kind != 0 && tid < 8) s_tok[tid] = inputs[r0 + tid];
    __syncthreads();

    #pragma unroll
    for (int it = 0; it < 2; it++) {
        int id = tid + it * 256;         // 0..511 float4 slots
        int r  = id >> 6;
        int q  = id & 63;
        const float* src = (kind == 0)
            ? ann + (size_t)(r0 + r) * H_
            : emb + (size_t)s_tok[r] * H_;
        float4 v = ((const float4*)src)[q];
        *(float4*)&a_s[r][q * 4] = v;
    }
    __syncthreads();

    const float* W; const float* bias;
    if (kind == 0)      { W = W1  + H_ * H_; bias = b1;  }
    else if (kind == 1) { W = Wiz + H_ * H_; bias = biz; }
    else if (kind == 2) { W = Wir + H_ * H_; bias = bir; }
    else                { W = Wih + H_ * H_; bias = bih; }

    const int j = tid;
    float acc[8];
    const float bj = bias[j];
    #pragma unroll
    for (int r = 0; r < 8; r++) acc[r] = bj;

    const float* Wj = W + j;
    #pragma unroll 4
    for (int k = 0; k < H_; k++) {
        float w = Wj[(size_t)k * H_];
        #pragma unroll
        for (int r = 0; r < 8; r++)
            acc[r] = fmaf(a_s[r][k], w, acc[r]);
    }

    if (kind == 0) {
        #pragma unroll
        for (int r = 0; r < 8; r++)
            g_annproj[(size_t)(r0 + r) * H_ + j] = acc[r];
    } else {
        const int g = kind - 1;
        #pragma unroll
        for (int r = 0; r < 8; r++)
            g_xWi[((size_t)(r0 + r) * 3 + g) * H_ + j] = acc[r];
    }
}

// =========================================================================
// Kernel 2: 64-step recurrent scan. One CTA per batch element, 256 threads.
// SMEM layout (floats):
// =========================================================================
#define SC_ANN 0
#define SC_AP  16384
#define SC_H   32768
#define SC_Q   33024
#define SC_HW  33280
#define SC_CTX 34048
#define SC_W2  34304
#define SC_U   34560
#define SC_AW  34624
#define SC_RED 34688
#define SC_TOT 34692
#define SCAN_SMEM_BYTES (SC_TOT * 4)

__global__ void __launch_bounds__(256, 1) scan_kernel(
    const float* __restrict__ ann,  const float* __restrict__ hinit,
    const float* __restrict__ W1,   const float* __restrict__ W2v,
    const float* __restrict__ b2,
    const float* __restrict__ Wiz,  const float* __restrict__ Wir,
    const float* __restrict__ Wih,
    const float* __restrict__ Whz,  const float* __restrict__ bhz,
    const float* __restrict__ Whr,  const float* __restrict__ bhr,
    const float* __restrict__ Whh,  const float* __restrict__ bhh,
    float* __restrict__ attn_out)
{
    extern __shared__ float sm[];
    float* s_ann = sm + SC_ANN;
    float* s_ap  = sm + SC_AP;
    float* s_h   = sm + SC_H;
    float* s_q   = sm + SC_Q;
    float* s_hw  = sm + SC_HW;
    float* s_ctx = sm + SC_CTX;
    float* s_w2  = sm + SC_W2;
    float* s_u   = sm + SC_U;
    float* s_aw  = sm + SC_AW;
    float* s_red = sm + SC_RED;

    const int b   = blockIdx.x;
    const int tid = threadIdx.x;
    const int j   = tid;

    {   // one-time loads: annotations + annproj tiles, h0, W2
        const float4* sa = (const float4*)(ann + (size_t)b * S_ * H_);
        const float4* sp = (const float4*)(g_annproj + (size_t)b * S_ * H_);
        #pragma unroll
        for (int i = 0; i < 16; i++) {
            int idx = tid + i * 256;
            ((float4*)s_ann)[idx] = sa[idx];
            ((float4*)s_ap)[idx]  = sp[idx];
        }
        s_h[j]  = hinit[(size_t)b * H_ + j];
        s_w2[j] = W2v[j];
    }
    __syncthreads();

    const float rbz = bhz[j], rbr = bhr[j], rbh = bhh[j];
    const float b2v = b2[0];
    const float* pW1  = W1  + j;
    const float* pWhz = Whz + j;
    const float* pWhr = Whr + j;
    const float* pWhh = Whh + j;
    const float* pWiz = Wiz + j;
    const float* pWir = Wir + j;
    const float* pWih = Wih + j;
    const int si = tid >> 2, p = tid & 3;

    for (int t = 0; t < T_; t++) {
        // ---- stage 1: q = h@W1[:H] ; hw_g = h@Wh_g + bh_g ----
        float aq = 0.f, az = rbz, ar = rbr, ah = rbh;
        #pragma unroll 4
        for (int k = 0; k < H_; k++) {
            float hk = s_h[k];
            aq = fmaf(hk, pW1 [(size_t)k * H_], aq);
            az = fmaf(hk, pWhz[(size_t)k * H_], az);
            ar = fmaf(hk, pWhr[(size_t)k * H_], ar);
            ah = fmaf(hk, pWhh[(size_t)k * H_], ah);
        }
        s_q[j] = aq;
        s_hw[j] = az; s_hw[H_ + j] = ar; s_hw[2 * H_ + j] = ah;
        __syncthreads();

        // ---- stage 2: scores u[s] = W2 . relu(q + annproj[s]) + b2 ----
        {
            float part = 0.f;
            #pragma unroll
            for (int i = 0; i < 64; i++) {
                int jj = p + 4 * ((i + si) & 63);   // bank-conflict-free rotation
                float v = s_q[jj] + s_ap[si * H_ + jj];
                v = fmaxf(v, 0.f);
                part = fmaf(v, s_w2[jj], part);
            }
            part += __shfl_xor_sync(0xffffffffu, part, 1);
            part += __shfl_xor_sync(0xffffffffu, part, 2);
            if (p == 0) s_u[si] = part + b2v;
        }
        __syncthreads();

        // ---- stage 3: softmax over 64 encoder positions ----
        float uv = (tid < 64) ? s_u[tid] : -1e30f;
        if (tid < 64) {
            float m = uv;
            #pragma unroll
            for (int o = 16; o > 0; o >>= 1)
                m = fmaxf(m, __shfl_xor_sync(0xffffffffu, m, o));
            if ((tid & 31) == 0) s_red[tid >> 5] = m;
        }
        __syncthreads();
        float gmax = fmaxf(s_red[0], s_red[1]);
        float ev = 0.f;
        if (tid < 64) {
            ev = __expf(uv - gmax);
            float ssum = ev;
            #pragma unroll
            for (int o = 16; o > 0; o >>= 1)
                ssum += __shfl_xor_sync(0xffffffffu, ssum, o);
            if ((tid & 31) == 0) s_red[2 + (tid >> 5)] = ssum;
        }
        __syncthreads();
        if (tid < 64) {
            float aw = ev / (s_red[2] + s_red[3]);
            s_aw[tid] = aw;
            attn_out[(size_t)b * S_ * T_ + (size_t)tid * T_ + t] = aw;
        }
        __syncthreads();

        // ---- stage 4: context[j] = sum_s aw[s]*ann[s][j] ----
        float ctx = 0.f;
        #pragma unroll
        for (int s2 = 0; s2 < 64; s2++)
            ctx = fmaf(s_aw[s2], s_ann[s2 * H_ + j], ctx);
        s_ctx[j] = ctx;
        __syncthreads();

        // ---- stage 5: ctx @ Wi*[:H] ----
        float cz = 0.f, cr = 0.f, ch = 0.f;
        #pragma unroll 4
        for (int k = 0; k < H_; k++) {
            float ck = s_ctx[k];
            cz = fmaf(ck, pWiz[(size_t)k * H_], cz);
            cr = fmaf(ck, pWir[(size_t)k * H_], cr);
            ch = fmaf(ck, pWih[(size_t)k * H_], ch);
        }

        // ---- stage 6: GRU gates ----
        const size_t xo = ((size_t)(b * T_ + t) * 3) * H_ + j;
        float xz = g_xWi[xo], xr = g_xWi[xo + H_], xh = g_xWi[xo + 2 * H_];
        float hprev = s_h[j];
        float z = 1.f / (1.f + __expf(-(cz + xz + s_hw[j])));
        float r = 1.f / (1.f + __expf(-(cr + xr + s_hw[H_ + j])));
        float g = tanhf(ch + xh + r * s_hw[2 * H_ + j]);
        float hn = (1.f - z) * g + z * hprev;
        s_h[j] = hn;                                    // only thread j reads slot j here
        g_hidden[(size_t)(b * T_ + t) * H_ + j] = hn;
        __syncthreads();
    }
}

// =========================================================================
// Kernel 3: output projection  out[B*T, V] = hiddens @ Wout + bout
// tf32 mma.sync m16n8k8. CTA tile 128(M)x64(N), 8 warps (4x2), warp 32x32.
// grid = (16 m-tiles fastest, 500 n-tiles) so Wout stays L2-resident.
// =========================================================================
__device__ __forceinline__ unsigned f2tf(float x) {
    unsigned r;
    asm("cvt.rna.tf32.f32 %0, %1;" : "=r"(r) : "f"(x));
    return r;
}

#define GBM 128
#define GBN 64
#define GBK 32
#define AS_STRIDE (GBM + 4)
#define BS_STRIDE (GBN + 4)

__global__ __launch_bounds__(256) void out_gemm_kernel(
    const float* __restrict__ Wout, const float* __restrict__ bout,
    float* __restrict__ out)
{
    __shared__ float As[GBK][AS_STRIDE];   // [k][m]
    __shared__ float Bs[GBK][BS_STRIDE];   // [k][n]

    const int tid  = threadIdx.x;
    const int wid  = tid >> 5;
    const int lane = tid & 31;
    const int g    = lane >> 2;
    const int tq   = lane & 3;
    const int wm   = wid & 3;     // 0..3 -> 32 rows each
    const int wn   = wid >> 2;    // 0..1 -> 32 cols each
    const int m0   = blockIdx.x * GBM;
    const int n0   = blockIdx.y * GBN;

    float c[2][4][4];
    #pragma unroll
    for (int a = 0; a < 2; a++)
        #pragma unroll
        for (int bb = 0; bb < 4; bb++)
            #pragma unroll
            for (int cc = 0; cc < 4; cc++) c[a][bb][cc] = 0.f;

    for (int kc = 0; kc < H_; kc += GBK) {
        #pragma unroll
        for (int it = 0; it < 4; it++) {            // A: 128x32
            int id = tid + it * 256;                // 0..1023
            int m  = id >> 3;
            int kq = id & 7;
            float4 v = *(const float4*)&g_hidden[(size_t)(m0 + m) * H_ + kc + kq * 4];
            As[kq * 4 + 0][m] = v.x;
            As[kq * 4 + 1][m] = v.y;
            As[kq * 4 + 2][m] = v.z;
            As[kq * 4 + 3][m] = v.w;
        }
        #pragma unroll
        for (int it = 0; it < 2; it++) {            // B: 32x64
            int id = tid + it * 256;                // 0..511
            int k  = id >> 4;
            int nq = id & 15;
            float4 v = *(const float4*)&Wout[(size_t)(kc + k) * V_ + n0 + nq * 4];
            *(float4*)&Bs[k][nq * 4] = v;
        }
        __syncthreads();

        #pragma unroll
        for (int ks = 0; ks < 4; ks++) {
            const int K0 = ks * 8;
            unsigned af[2][4];
            #pragma unroll
            for (int mt = 0; mt < 2; mt++) {
                int row = wm * 32 + mt * 16;
                af[mt][0] = f2tf(As[K0 + tq    ][row + g    ]);
                af[mt][1] = f2tf(As[K0 + tq    ][row + g + 8]);
                af[mt][2] = f2tf(As[K0 + tq + 4][row + g    ]);
                af[mt][3] = f2tf(As[K0 + tq + 4][row + g + 8]);
            }
            unsigned bf[4][2];
            #pragma unroll
            for (int nt = 0; nt < 4; nt++) {
                int col = wn * 32 + nt * 8 + g;
                bf[nt][0] = f2tf(Bs[K0 + tq    ][col]);
                bf[nt][1] = f2tf(Bs[K0 + tq + 4][col]);
            }
            #pragma unroll
            for (int mt = 0; mt < 2; mt++)
                #pragma unroll
                for (int nt = 0; nt < 4; nt++) {
                    asm volatile(
                        "mma.sync.aligned.m16n8k8.row.col.f32.tf32.tf32.f32 "
                        "{%0,%1,%2,%3}, {%4,%5,%6,%7}, {%8,%9}, {%0,%1,%2,%3};"
                        : "+f"(c[mt][nt][0]), "+f"(c[mt][nt][1]),
                          "+f"(c[mt][nt][2]), "+f"(c[mt][nt][3])
                        : "r"(af[mt][0]), "r"(af[mt][1]),
                          "r"(af[mt][2]), "r"(af[mt][3]),
                          "r"(bf[nt][0]), "r"(bf[nt][1]));
                }
        }
        __syncthreads();
    }

    #pragma unroll
    for (int mt = 0; mt < 2; mt++) {
        #pragma unroll
        for (int nt = 0; nt < 4; nt++) {
            int row = m0 + wm * 32 + mt * 16 + g;
            int col = n0 + wn * 32 + nt * 8 + 2 * tq;
            float bo0 = bout[col], bo1 = bout[col + 1];
            float2 v0 = make_float2(c[mt][nt][0] + bo0, c[mt][nt][1] + bo1);
            float2 v1 = make_float2(c[mt][nt][2] + bo0, c[mt][nt][3] + bo1);
            *(float2*)&out[(size_t)row * V_ + col]       = v0;
            *(float2*)&out[(size_t)(row + 8) * V_ + col] = v1;
        }
    }
}

// =========================================================================
extern "C" void kernel_launch(void* const* d_in, const int* in_sizes, int n_in,
                              void* d_out, int out_size)
{
    const int*   inputs = (const int*)  d_in[0];
    const float* ann    = (const float*)d_in[1];
    const float* hinit  = (const float*)d_in[2];
    const float* emb    = (const float*)d_in[3];
    const float* W1     = (const float*)d_in[4];
    const float* b1     = (const float*)d_in[5];
    const float* W2v    = (const float*)d_in[6];
    const float* b2     = (const float*)d_in[7];
    const float* Wiz    = (const float*)d_in[8];
    const float* biz    = (const float*)d_in[9];
    const float* Wir    = (const float*)d_in[10];
    const float* bir    = (const float*)d_in[11];
    const float* Wih    = (const float*)d_in[12];
    const float* bih    = (const float*)d_in[13];
    const float* Whz    = (const float*)d_in[14];
    const float* bhz    = (const float*)d_in[15];
    const float* Whr    = (const float*)d_in[16];
    const float* bhr    = (const float*)d_in[17];
    const float* Whh    = (const float*)d_in[18];
    const float* bhh    = (const float*)d_in[19];
    const float* Wout   = (const float*)d_in[20];
    const float* bout   = (const float*)d_in[21];

    float* out  = (float*)d_out;
    float* attn = out + (size_t)B_ * T_ * V_;   // outputs concatenated: (B,T,V) then (B,S,T)

    cudaFuncSetAttribute(scan_kernel,
                         cudaFuncAttributeMaxDynamicSharedMemorySize,
                         SCAN_SMEM_BYTES);

    prep_kernel<<<1024, 256>>>(inputs, ann, emb, W1, b1,
                               Wiz, biz, Wir, bir, Wih, bih);
    scan_kernel<<<B_, 256, SCAN_SMEM_BYTES>>>(ann, hinit, W1, W2v, b2,
                                              Wiz, Wir, Wih,
                                              Whz, bhz, Whr, bhr, Whh, bhh,
                                              attn);
    out_gemm_kernel<<<dim3(16, 500), 256>>>(Wout, bout, out);
}

// round 7
// speedup vs baseline: 1.8908x; 1.8908x over previous
#include <cuda_runtime.h>
#include <cuda_bf16.h>
#include <cstdint>
#include <cstddef>

#define B_ 32
#define T_ 64
#define S_ 64
#define H_ 256
#define V_ 32000

// ---------------- device scratch (no runtime allocations allowed) ----------------
__device__ __align__(16) float g_annproj[B_ * S_ * H_];      // ann @ W1[H:] + b1
__device__ __align__(16) float g_xWi[B_ * T_ * 3 * H_];      // emb[tok] @ Wi*[H:] + bi*
__device__ __align__(16) float g_hidden[B_ * T_ * H_];       // scan outputs, tf32-rounded
__device__ __align__(16) float g_wout[(size_t)H_ * V_];      // Wout, tf32-rounded

__device__ __forceinline__ float f2tf_val(float x) {
    unsigned r;
    asm("cvt.rna.tf32.f32 %0, %1;" : "=r"(r) : "f"(x));
    return __uint_as_float(r);
}

// =========================================================================
// Kernel 1: precompute annproj and xWi.  16 output rows per block.
// grid.x = 512: kind = bid>>7 (0=ann,1=z,2=r,3=h), tile = bid&127.
// =========================================================================
__global__ __launch_bounds__(256) void prep_kernel(
    const int* __restrict__ inputs, const float* __restrict__ ann,
    const float* __restrict__ emb,
    const float* __restrict__ W1,  const float* __restrict__ b1,
    const float* __restrict__ Wiz, const float* __restrict__ biz,
    const float* __restrict__ Wir, const float* __restrict__ bir,
    const float* __restrict__ Wih, const float* __restrict__ bih)
{
    __shared__ float a_s[16][H_];
    __shared__ int s_tok[16];
    const int tid  = threadIdx.x;
    const int kind = blockIdx.x >> 7;
    const int r0   = (blockIdx.x & 127) * 16;

    if (kind != 0 && tid < 16) s_tok[tid] = inputs[r0 + tid];
    __syncthreads();

    #pragma unroll
    for (int it = 0; it < 4; it++) {
        int id = tid + it * 256;          // 0..1023 float4 slots
        int r  = id >> 6;
        int q  = id & 63;
        const float* src = (kind == 0)
            ? ann + (size_t)(r0 + r) * H_
            : emb + (size_t)s_tok[r] * H_;
        ((float4*)&a_s[r][0])[q] = ((const float4*)src)[q];
    }
    __syncthreads();

    const float* W; const float* bias;
    if (kind == 0)      { W = W1  + H_ * H_; bias = b1;  }
    else if (kind == 1) { W = Wiz + H_ * H_; bias = biz; }
    else if (kind == 2) { W = Wir + H_ * H_; bias = bir; }
    else                { W = Wih + H_ * H_; bias = bih; }

    const int j = tid;
    float acc[16];
    const float bj = bias[j];
    #pragma unroll
    for (int r = 0; r < 16; r++) acc[r] = bj;

    const float* Wj = W + j;
    #pragma unroll 2
    for (int k4 = 0; k4 < H_ / 4; k4++) {
        float w0 = Wj[(size_t)(4 * k4 + 0) * H_];
        float w1 = Wj[(size_t)(4 * k4 + 1) * H_];
        float w2 = Wj[(size_t)(4 * k4 + 2) * H_];
        float w3 = Wj[(size_t)(4 * k4 + 3) * H_];
        #pragma unroll
        for (int r = 0; r < 16; r++) {
            float4 a4 = *(const float4*)&a_s[r][k4 * 4];
            acc[r] = fmaf(a4.x, w0, acc[r]);
            acc[r] = fmaf(a4.y, w1, acc[r]);
            acc[r] = fmaf(a4.z, w2, acc[r]);
            acc[r] = fmaf(a4.w, w3, acc[r]);
        }
    }

    if (kind == 0) {
        #pragma unroll
        for (int r = 0; r < 16; r++)
            g_annproj[(size_t)(r0 + r) * H_ + j] = acc[r];
    } else {
        const int g = kind - 1;
        #pragma unroll
        for (int r = 0; r < 16; r++)
            g_xWi[((size_t)(r0 + r) * 3 + g) * H_ + j] = acc[r];
    }
}

// =========================================================================
// Kernel 1b: round Wout to tf32 once (mma then sees exactly RNA-rounded B).
// grid 8000 x 256, one float4 per thread.
// =========================================================================
__global__ __launch_bounds__(256) void wout_cvt_kernel(const float* __restrict__ Wout)
{
    size_t idx = ((size_t)blockIdx.x * 256 + threadIdx.x) * 4;
    float4 v = *(const float4*)(Wout + idx);
    v.x = f2tf_val(v.x); v.y = f2tf_val(v.y);
    v.z = f2tf_val(v.z); v.w = f2tf_val(v.w);
    *(float4*)(g_wout + idx) = v;
}

// =========================================================================
// Kernel 2: 64-step recurrent scan. One CTA per batch element, 512 threads.
// Weights loaded as float4 (LDG.128), k-dim split in 2 for MLP.
// =========================================================================
#define SC_ANN 0
#define SC_AP  16384
#define SC_H   32768
#define SC_Q   33024
#define SC_HW  33280
#define SC_CTX 34048
#define SC_W2  34304
#define SC_U   34560
#define SC_AW  34624
#define SC_RED 34688
#define SC_P1  34692   /* 1024 floats: stage-1 k-partials; reused as s_ci */
#define SC_P5  35716   /* 768 floats: stage-5 k-partials */
#define SC_TOT 36484
#define SCAN_SMEM_BYTES (SC_TOT * 4)

__global__ void __launch_bounds__(512, 1) scan_kernel(
    const float* __restrict__ ann,  const float* __restrict__ hinit,
    const float* __restrict__ W1,   const float* __restrict__ W2v,
    const float* __restrict__ b2,
    const float* __restrict__ Wiz,  const float* __restrict__ Wir,
    const float* __restrict__ Wih,
    const float* __restrict__ Whz,  const float* __restrict__ bhz,
    const float* __restrict__ Whr,  const float* __restrict__ bhr,
    const float* __restrict__ Whh,  const float* __restrict__ bhh,
    float* __restrict__ attn_out)
{
    extern __shared__ float sm[];
    float* s_ann = sm + SC_ANN;
    float* s_ap  = sm + SC_AP;
    float* s_h   = sm + SC_H;
    float* s_q   = sm + SC_Q;
    float* s_hw  = sm + SC_HW;
    float* s_ctx = sm + SC_CTX;
    float* s_w2  = sm + SC_W2;
    float* s_u   = sm + SC_U;
    float* s_aw  = sm + SC_AW;
    float* s_red = sm + SC_RED;
    float* s_p1  = sm + SC_P1;
    float* s_ci  = sm + SC_P1;   // alias: stage-5 combined results
    float* s_p5  = sm + SC_P5;

    const int b   = blockIdx.x;
    const int tid = threadIdx.x;

    {   // one-time loads
        const float4* sa = (const float4*)(ann + (size_t)b * S_ * H_);
        const float4* sp = (const float4*)(g_annproj + (size_t)b * S_ * H_);
        #pragma unroll
        for (int i = 0; i < 8; i++) {
            int idx = tid + i * 512;
            ((float4*)s_ann)[idx] = sa[idx];
            ((float4*)s_ap)[idx]  = sp[idx];
        }
        if (tid < 256) {
            s_h[tid]  = hinit[(size_t)b * H_ + tid];
            s_w2[tid] = W2v[tid];
        }
    }
    __syncthreads();

    // ---- stage-1 role: m1 in {W1,Whz,Whr,Whh}, kh1 = k-half, c1 = col/4 ----
    const int m1  = tid >> 7;
    const int kh1 = (tid >> 6) & 1;
    const int c1  = tid & 63;
    const float* Wm1 = (m1 == 0 ? W1 : m1 == 1 ? Whz : m1 == 2 ? Whr : Whh)
                       + 4 * c1 + (size_t)(kh1 * 128) * H_;
    const int k01 = kh1 * 128;
    float4 bias1 = make_float4(0.f, 0.f, 0.f, 0.f);
    if (kh1 == 0 && m1 >= 1) {
        const float* bp = (m1 == 1 ? bhz : m1 == 2 ? bhr : bhh) + 4 * c1;
        bias1 = *(const float4*)bp;
    }

    // ---- stage-5 role (tid < 384): m5 in {Wiz,Wir,Wih} ----
    const int m5  = tid >> 7;                 // 0..2 valid when tid<384
    const int kh5 = (tid >> 6) & 1;
    const int c5  = tid & 63;
    const float* Wm5 = (m5 == 0 ? Wiz : m5 == 1 ? Wir : Wih)
                       + 4 * c5 + (size_t)(kh5 * 128) * H_;
    const int k05 = kh5 * 128;

    const int si = tid >> 3, p = tid & 7;     // stage-2 role
    const float b2v = b2[0];

    for (int t = 0; t < T_; t++) {
        // ================= stage 1: q = h@W1a ; hw_g = h@Wh_g + bh_g =======
        {
            float4 acc = make_float4(0.f, 0.f, 0.f, 0.f);
            const float* wp = Wm1;
            #pragma unroll 4
            for (int k = 0; k < 128; k++) {
                float hk = s_h[k01 + k];
                float4 w = *(const float4*)(wp);
                wp += H_;
                acc.x = fmaf(hk, w.x, acc.x);
                acc.y = fmaf(hk, w.y, acc.y);
                acc.z = fmaf(hk, w.z, acc.z);
                acc.w = fmaf(hk, w.w, acc.w);
            }
            if (kh1 == 1) *(float4*)&s_p1[(m1 * 64 + c1) * 4] = acc;
            __syncthreads();
            if (kh1 == 0) {
                float4 o = *(const float4*)&s_p1[(m1 * 64 + c1) * 4];
                o.x += acc.x + bias1.x; o.y += acc.y + bias1.y;
                o.z += acc.z + bias1.z; o.w += acc.w + bias1.w;
                if (m1 == 0) *(float4*)&s_q[4 * c1] = o;
                else         *(float4*)&s_hw[(m1 - 1) * H_ + 4 * c1] = o;
            }
        }
        __syncthreads();

        // ================= stage 2: u[s] = W2 . relu(q + ap[s]) + b2 =======
        {
            float part = 0.f;
            #pragma unroll
            for (int i = 0; i < 32; i++) {
                int jj = p + 8 * ((i + si) & 31);     // conflict-free rotation
                float v = s_q[jj] + s_ap[si * H_ + jj];
                v = fmaxf(v, 0.f);
                part = fmaf(v, s_w2[jj], part);
            }
            part += __shfl_xor_sync(0xffffffffu, part, 1);
            part += __shfl_xor_sync(0xffffffffu, part, 2);
            part += __shfl_xor_sync(0xffffffffu, part, 4);
            if (p == 0) s_u[si] = part + b2v;
        }
        __syncthreads();

        // ================= stage 3: softmax over 64 positions ==============
        float uv = (tid < 64) ? s_u[tid] : -1e30f;
        if (tid < 64) {
            float m = uv;
            #pragma unroll
            for (int o = 16; o > 0; o >>= 1)
                m = fmaxf(m, __shfl_xor_sync(0xffffffffu, m, o));
            if ((tid & 31) == 0) s_red[tid >> 5] = m;
        }
        __syncthreads();
        float gmax = fmaxf(s_red[0], s_red[1]);
        float ev = 0.f;
        if (tid < 64) {
            ev = __expf(uv - gmax);
            float ssum = ev;
            #pragma unroll
            for (int o = 16; o > 0; o >>= 1)
                ssum += __shfl_xor_sync(0xffffffffu, ssum, o);
            if ((tid & 31) == 0) s_red[2 + (tid >> 5)] = ssum;
        }
        __syncthreads();
        if (tid < 64) {
            float aw = ev / (s_red[2] + s_red[3]);
            s_aw[tid] = aw;
            attn_out[(size_t)b * S_ * T_ + (size_t)tid * T_ + t] = aw;
        }
        __syncthreads();

        // ================= stage 4: context ================================
        if (tid < 256) {
            float ctx = 0.f;
            #pragma unroll
            for (int s2 = 0; s2 < 64; s2++)
                ctx = fmaf(s_aw[s2], s_ann[s2 * H_ + tid], ctx);
            s_ctx[tid] = ctx;
        }
        // prefetch xWi for stage 6 (hides global latency behind stage 5)
        float xz = 0.f, xr = 0.f, xh = 0.f;
        if (tid < 256) {
            const size_t xo = ((size_t)(b * T_ + t) * 3) * H_ + tid;
            xz = g_xWi[xo]; xr = g_xWi[xo + H_]; xh = g_xWi[xo + 2 * H_];
        }
        __syncthreads();

        // ================= stage 5: ctx @ Wi*[:H] ==========================
        if (tid < 384) {
            float4 acc = make_float4(0.f, 0.f, 0.f, 0.f);
            const float* wp = Wm5;
            #pragma unroll 4
            for (int k = 0; k < 128; k++) {
                float ck = s_ctx[k05 + k];
                float4 w = *(const float4*)(wp);
                wp += H_;
                acc.x = fmaf(ck, w.x, acc.x);
                acc.y = fmaf(ck, w.y, acc.y);
                acc.z = fmaf(ck, w.z, acc.z);
                acc.w = fmaf(ck, w.w, acc.w);
            }
            if (kh5 == 1) *(float4*)&s_p5[(m5 * 64 + c5) * 4] = acc;
            __syncthreads();
            if (kh5 == 0) {
                float4 o = *(const float4*)&s_p5[(m5 * 64 + c5) * 4];
                o.x += acc.x; o.y += acc.y; o.z += acc.z; o.w += acc.w;
                *(float4*)&s_ci[m5 * H_ + 4 * c5] = o;
            }
        } else {
            __syncthreads();
        }
        __syncthreads();

        // ================= stage 6: GRU gates ==============================
        if (tid < 256) {
            const int j = tid;
            float hprev = s_h[j];
            float z = 1.f / (1.f + __expf(-(s_ci[j]           + xz + s_hw[j])));
            float r = 1.f / (1.f + __expf(-(s_ci[H_ + j]      + xr + s_hw[H_ + j])));
            float g = tanhf(s_ci[2 * H_ + j] + xh + r * s_hw[2 * H_ + j]);
            float hn = (1.f - z) * g + z * hprev;
            s_h[j] = hn;
            g_hidden[(size_t)(b * T_ + t) * H_ + j] = f2tf_val(hn);
        }
        __syncthreads();
    }
}

// =========================================================================
// Kernel 3: out[B*T, V] = hiddens @ Wout + bout   (operands pre-rounded tf32)
// tf32 mma m16n8k8, CTA tile 128x64, cp.async double-buffered.
// =========================================================================
#define GBM 128
#define GBN 64
#define GBK 32
#define AS_STRIDE 36   /* [m][k] layout, conflict-free fragment loads */
#define BS_STRIDE 72   /* [k][n] layout */
#define GEMM_SMEM_FLOATS (2 * GBM * AS_STRIDE + 2 * GBK * BS_STRIDE)
#define GEMM_SMEM_BYTES  (GEMM_SMEM_FLOATS * 4)

__device__ __forceinline__ void cpasync16(void* smem_dst, const void* gsrc) {
    unsigned s = (unsigned)__cvta_generic_to_shared(smem_dst);
    asm volatile("cp.async.ca.shared.global [%0], [%1], 16;" :: "r"(s), "l"(gsrc));
}

__global__ __launch_bounds__(256) void out_gemm_kernel(
    const float* __restrict__ bout, float* __restrict__ out)
{
    extern __shared__ float gsm[];
    float* As = gsm;                              // [2][GBM][AS_STRIDE]
    float* Bs = gsm + 2 * GBM * AS_STRIDE;        // [2][GBK][BS_STRIDE]

    const int tid  = threadIdx.x;
    const int wid  = tid >> 5;
    const int lane = tid & 31;
    const int g    = lane >> 2;
    const int tq   = lane & 3;
    const int wm   = wid & 3;
    const int wn   = wid >> 2;
    const int m0   = blockIdx.x * GBM;
    const int n0   = blockIdx.y * GBN;

    float c[2][4][4];
    #pragma unroll
    for (int a = 0; a < 2; a++)
        #pragma unroll
        for (int bb = 0; bb < 4; bb++)
            #pragma unroll
            for (int cc = 0; cc < 4; cc++) c[a][bb][cc] = 0.f;

    auto issue = [&](int kc_i) {
        const int kc = kc_i * GBK;
        float* Ab = As + (kc_i & 1) * GBM * AS_STRIDE;
        float* Bb = Bs + (kc_i & 1) * GBK * BS_STRIDE;
        #pragma unroll
        for (int it = 0; it < 4; it++) {          // A: 128x32 as [m][k]
            int id = tid + it * 256;              // 0..1023
            int m  = id >> 3;
            int q  = id & 7;
            cpasync16(&Ab[m * AS_STRIDE + q * 4],
                      &g_hidden[(size_t)(m0 + m) * H_ + kc + q * 4]);
        }
        #pragma unroll
        for (int it = 0; it < 2; it++) {          // B: 32x64 as [k][n]
            int id = tid + it * 256;              // 0..511
            int k  = id >> 4;
            int nq = id & 15;
            cpasync16(&Bb[k * BS_STRIDE + nq * 4],
                      &g_wout[(size_t)(kc + k) * V_ + n0 + nq * 4]);
        }
        asm volatile("cp.async.commit_group;");
    };

    issue(0);

    for (int kc_i = 0; kc_i < H_ / GBK; kc_i++) {
        if (kc_i + 1 < H_ / GBK) {
            issue(kc_i + 1);
            asm volatile("cp.async.wait_group 1;");
        } else {
            asm volatile("cp.async.wait_group 0;");
        }
        __syncthreads();

        const float* Ab = As + (kc_i & 1) * GBM * AS_STRIDE;
        const float* Bb = Bs + (kc_i & 1) * GBK * BS_STRIDE;

        #pragma unroll
        for (int ks = 0; ks < 4; ks++) {
            const int K0 = ks * 8;
            unsigned af[2][4];
            #pragma unroll
            for (int mt = 0; mt < 2; mt++) {
                int row = wm * 32 + mt * 16 + g;
                af[mt][0] = __float_as_uint(Ab[(row    ) * AS_STRIDE + K0 + tq    ]);
                af[mt][1] = __float_as_uint(Ab[(row + 8) * AS_STRIDE + K0 + tq    ]);
                af[mt][2] = __float_as_uint(Ab[(row    ) * AS_STRIDE + K0 + tq + 4]);
                af[mt][3] = __float_as_uint(Ab[(row + 8) * AS_STRIDE + K0 + tq + 4]);
            }
            unsigned bf[4][2];
            #pragma unroll
            for (int nt = 0; nt < 4; nt++) {
                int col = wn * 32 + nt * 8 + g;
                bf[nt][0] = __float_as_uint(Bb[(K0 + tq    ) * BS_STRIDE + col]);
                bf[nt][1] = __float_as_uint(Bb[(K0 + tq + 4) * BS_STRIDE + col]);
            }
            #pragma unroll
            for (int mt = 0; mt < 2; mt++)
                #pragma unroll
                for (int nt = 0; nt < 4; nt++) {
                    asm volatile(
                        "mma.sync.aligned.m16n8k8.row.col.f32.tf32.tf32.f32 "
                        "{%0,%1,%2,%3}, {%4,%5,%6,%7}, {%8,%9}, {%0,%1,%2,%3};"
                        : "+f"(c[mt][nt][0]), "+f"(c[mt][nt][1]),
                          "+f"(c[mt][nt][2]), "+f"(c[mt][nt][3])
                        : "r"(af[mt][0]), "r"(af[mt][1]),
                          "r"(af[mt][2]), "r"(af[mt][3]),
                          "r"(bf[nt][0]), "r"(bf[nt][1]));
                }
        }
        __syncthreads();
    }

    #pragma unroll
    for (int mt = 0; mt < 2; mt++) {
        #pragma unroll
        for (int nt = 0; nt < 4; nt++) {
            int row = m0 + wm * 32 + mt * 16 + g;
            int col = n0 + wn * 32 + nt * 8 + 2 * tq;
            float bo0 = bout[col], bo1 = bout[col + 1];
            float2 v0 = make_float2(c[mt][nt][0] + bo0, c[mt][nt][1] + bo1);
            float2 v1 = make_float2(c[mt][nt][2] + bo0, c[mt][nt][3] + bo1);
            *(float2*)&out[(size_t)row * V_ + col]       = v0;
            *(float2*)&out[(size_t)(row + 8) * V_ + col] = v1;
        }
    }
}

// =========================================================================
extern "C" void kernel_launch(void* const* d_in, const int* in_sizes, int n_in,
                              void* d_out, int out_size)
{
    const int*   inputs = (const int*)  d_in[0];
    const float* ann    = (const float*)d_in[1];
    const float* hinit  = (const float*)d_in[2];
    const float* emb    = (const float*)d_in[3];
    const float* W1     = (const float*)d_in[4];
    const float* b1     = (const float*)d_in[5];
    const float* W2v    = (const float*)d_in[6];
    const float* b2     = (const float*)d_in[7];
    const float* Wiz    = (const float*)d_in[8];
    const float* biz    = (const float*)d_in[9];
    const float* Wir    = (const float*)d_in[10];
    const float* bir    = (const float*)d_in[11];
    const float* Wih    = (const float*)d_in[12];
    const float* bih    = (const float*)d_in[13];
    const float* Whz    = (const float*)d_in[14];
    const float* bhz    = (const float*)d_in[15];
    const float* Whr    = (const float*)d_in[16];
    const float* bhr    = (const float*)d_in[17];
    const float* Whh    = (const float*)d_in[18];
    const float* bhh    = (const float*)d_in[19];
    const float* Wout   = (const float*)d_in[20];
    const float* bout   = (const float*)d_in[21];

    float* out  = (float*)d_out;
    float* attn = out + (size_t)B_ * T_ * V_;   // outputs: (B,T,V) then (B,S,T)

    cudaFuncSetAttribute(scan_kernel,
                         cudaFuncAttributeMaxDynamicSharedMemorySize,
                         SCAN_SMEM_BYTES);
    cudaFuncSetAttribute(out_gemm_kernel,
                         cudaFuncAttributeMaxDynamicSharedMemorySize,
                         GEMM_SMEM_BYTES);

    prep_kernel<<<512, 256>>>(inputs, ann, emb, W1, b1,
                              Wiz, biz, Wir, bir, Wih, bih);
    wout_cvt_kernel<<<8000, 256>>>(Wout);
    scan_kernel<<<B_, 512, SCAN_SMEM_BYTES>>>(ann, hinit, W1, W2v, b2,
                                              Wiz, Wir, Wih,
                                              Whz, bhz, Whr, bhr, Whh, bhh,
                                              attn);
    out_gemm_kernel<<<dim3(16, 500), 256, GEMM_SMEM_BYTES>>>(bout, out);
}